// round 1
// baseline (speedup 1.0000x reference)
#include <cuda_runtime.h>
#include <math.h>

#define B_SZ    2
#define T_SEQ   2048
#define D_MODEL 2048
#define N_HEADS 16
#define N_KV    4
#define HD      128

// ---------------- scratch (static device globals; no allocs) ----------------
__device__ float g_q[(size_t)B_SZ * N_HEADS * T_SEQ * HD];   // [b,h,t,d] 32MB
__device__ float g_k[(size_t)B_SZ * N_KV   * T_SEQ * HD];    // [b,kv,t,d] 8MB
__device__ float g_v[(size_t)B_SZ * N_KV   * T_SEQ * HD];    // 8MB
__device__ float g_attn[(size_t)B_SZ * T_SEQ * N_HEADS * HD];// [b,t,h,d] 32MB

// ---------------- SGEMM: C[M,N] = A[M,K] @ Bw[N,K]^T ----------------
// MODE 0: C[row*N+col]   MODE 1: scatter to [b, h, t, d] with h=col/128
template<int MODE>
__global__ __launch_bounds__(256)
void sgemm_tn(const float* __restrict__ A, const float* __restrict__ Bw,
              float* __restrict__ C, int M, int N, int K, int H)
{
    __shared__ float As[8][128];
    __shared__ float Bs[8][128];
    const int bm0 = blockIdx.y * 128;
    const int bn0 = blockIdx.x * 128;
    const int t  = threadIdx.x;
    const int ty = t >> 4;          // 0..15
    const int tx = t & 15;          // 0..15
    const int lrow = t >> 1;        // 0..127
    const int lk   = (t & 1) * 4;   // 0 or 4

    const float* Ap = A  + (size_t)(bm0 + lrow) * K + lk;
    const float* Bp = Bw + (size_t)(bn0 + lrow) * K + lk;

    float acc[8][8];
    #pragma unroll
    for (int i = 0; i < 8; i++)
        #pragma unroll
        for (int j = 0; j < 8; j++) acc[i][j] = 0.f;

    for (int k0 = 0; k0 < K; k0 += 8) {
        float4 av = *(const float4*)(Ap + k0);
        float4 bv = *(const float4*)(Bp + k0);
        __syncthreads();
        As[lk+0][lrow] = av.x; As[lk+1][lrow] = av.y;
        As[lk+2][lrow] = av.z; As[lk+3][lrow] = av.w;
        Bs[lk+0][lrow] = bv.x; Bs[lk+1][lrow] = bv.y;
        Bs[lk+2][lrow] = bv.z; Bs[lk+3][lrow] = bv.w;
        __syncthreads();
        #pragma unroll
        for (int kk = 0; kk < 8; kk++) {
            float a[8], b[8];
            *(float4*)(a)   = *(const float4*)&As[kk][ty*8];
            *(float4*)(a+4) = *(const float4*)&As[kk][ty*8+4];
            *(float4*)(b)   = *(const float4*)&Bs[kk][tx*8];
            *(float4*)(b+4) = *(const float4*)&Bs[kk][tx*8+4];
            #pragma unroll
            for (int i = 0; i < 8; i++)
                #pragma unroll
                for (int j = 0; j < 8; j++)
                    acc[i][j] += a[i] * b[j];
        }
    }

    #pragma unroll
    for (int i = 0; i < 8; i++) {
        int row = bm0 + ty*8 + i;
        #pragma unroll
        for (int j4 = 0; j4 < 2; j4++) {
            int col = bn0 + tx*8 + j4*4;
            float4 v = make_float4(acc[i][j4*4+0], acc[i][j4*4+1],
                                   acc[i][j4*4+2], acc[i][j4*4+3]);
            if (MODE == 0) {
                *(float4*)&C[(size_t)row * N + col] = v;
            } else {
                int b  = row >> 11;            // / T_SEQ
                int tq = row & (T_SEQ - 1);
                int h  = col >> 7;             // / HD
                int d  = col & (HD - 1);
                size_t idx = (((size_t)b * H + h) * T_SEQ + tq) * HD + d;
                *(float4*)&C[idx] = v;
            }
        }
    }
}

// ---------------- RoPE (in place, layout [b, heads, t, d]) ----------------
__global__ void rope_kernel(float* __restrict__ x, long total_pairs)
{
    long idx = (long)blockIdx.x * blockDim.x + threadIdx.x;
    if (idx >= total_pairs) return;
    int  i   = (int)(idx & 63);        // 0..63 (even-dim index)
    long row = idx >> 6;               // (b*heads + h)*T + t
    int  tpos = (int)(row & (T_SEQ - 1));
    float* p = x + row * HD;
    // inv_freq = theta^(-2i/128); match reference within fp32 rounding
    double inv = exp(-((double)i / 64.0) * 13.815510557964274);  // ln(1e6)
    double sd, cd;
    sincos((double)tpos * inv, &sd, &cd);
    float c = (float)cd, s = (float)sd;
    float x1 = p[i], x2 = p[i + 64];
    p[i]      = x1 * c - x2 * s;
    p[i + 64] = x2 * c + x1 * s;
}

// ---------------- Flash attention (fp32, causal, GQA) ----------------
#define BM 64
#define BN 64
#define KSTR 132   // row stride for Qs/Ks/Vs (bank-conflict-free)
#define PSTR 65
#define SM_ATT ((3 * BM * KSTR + BM * PSTR) * 4)

__global__ __launch_bounds__(256)
void attn_kernel(const float* __restrict__ q, const float* __restrict__ k,
                 const float* __restrict__ v, float* __restrict__ out)
{
    extern __shared__ float smem[];
    float* Qs = smem;
    float* Ks = Qs + BM * KSTR;
    float* Vs = Ks + BM * KSTR;
    float* Ps = Vs + BM * KSTR;

    const int qt = (gridDim.x - 1) - blockIdx.x;   // big tiles first
    const int bh = blockIdx.y;
    const int b  = bh / N_HEADS;
    const int h  = bh % N_HEADS;
    const int kvh = h / (N_HEADS / N_KV);

    const float* qb = q + ((size_t)bh * T_SEQ + (size_t)qt * BM) * HD;
    const float* kb = k + ((size_t)(b * N_KV + kvh)) * T_SEQ * HD;
    const float* vb = v + ((size_t)(b * N_KV + kvh)) * T_SEQ * HD;

    const int t = threadIdx.x;
    const int r = t >> 2;    // q-row within tile, 0..63
    const int g = t & 3;     // column group, 0..3

    // load Q tile
    for (int i = t; i < BM * (HD / 4); i += 256) {
        int rr = i >> 5;
        int c4 = (i & 31) * 4;
        *(float4*)&Qs[rr * KSTR + c4] = *(const float4*)(qb + (size_t)rr * HD + c4);
    }

    float m = -3.0e38f, l = 0.f;
    float acc[32];
    #pragma unroll
    for (int i = 0; i < 32; i++) acc[i] = 0.f;

    const float scale = 0.08838834764831845f;   // 1/sqrt(128)
    const int qrow = qt * BM + r;

    for (int kt = 0; kt <= qt; kt++) {
        __syncthreads();
        for (int i = t; i < BN * (HD / 4); i += 256) {
            int rr = i >> 5;
            int c4 = (i & 31) * 4;
            size_t go = ((size_t)(kt * BN + rr)) * HD + c4;
            *(float4*)&Ks[rr * KSTR + c4] = *(const float4*)(kb + go);
            *(float4*)&Vs[rr * KSTR + c4] = *(const float4*)(vb + go);
        }
        __syncthreads();

        // scores: this thread covers k-cols j = 4*jj + g, jj = 0..15 (interleaved)
        float s[16];
        #pragma unroll
        for (int j = 0; j < 16; j++) s[j] = 0.f;
        #pragma unroll 4
        for (int d4 = 0; d4 < 32; d4++) {
            float4 qv = *(const float4*)&Qs[r * KSTR + d4 * 4];
            #pragma unroll
            for (int j = 0; j < 16; j++) {
                float4 kv = *(const float4*)&Ks[(4 * j + g) * KSTR + d4 * 4];
                s[j] += qv.x * kv.x + qv.y * kv.y + qv.z * kv.z + qv.w * kv.w;
            }
        }

        const bool diag = (kt == qt);
        float mloc = -3.0e38f;
        #pragma unroll
        for (int j = 0; j < 16; j++) {
            float sv = s[j] * scale;
            if (diag && (4 * j + g) > r) sv = -3.0e38f;
            s[j] = sv;
            mloc = fmaxf(mloc, sv);
        }
        mloc = fmaxf(mloc, __shfl_xor_sync(0xffffffffu, mloc, 1));
        mloc = fmaxf(mloc, __shfl_xor_sync(0xffffffffu, mloc, 2));
        float mnew = fmaxf(m, mloc);
        float corr = __expf(m - mnew);
        float psum = 0.f;
        #pragma unroll
        for (int j = 0; j < 16; j++) {
            float p = __expf(s[j] - mnew);
            psum += p;
            Ps[r * PSTR + 4 * j + g] = p;
        }
        psum += __shfl_xor_sync(0xffffffffu, psum, 1);
        psum += __shfl_xor_sync(0xffffffffu, psum, 2);
        l = l * corr + psum;
        m = mnew;
        #pragma unroll
        for (int i = 0; i < 32; i++) acc[i] *= corr;

        __syncwarp();   // Ps produced/consumed within each row's 4-lane group (same warp)

        // PV: acc cols are float4 groups (g + 4*i)*4, i = 0..7
        #pragma unroll 2
        for (int j = 0; j < BN; j++) {
            float p = Ps[r * PSTR + j];
            #pragma unroll
            for (int i = 0; i < 8; i++) {
                float4 vv = *(const float4*)&Vs[j * KSTR + (g + 4 * i) * 4];
                acc[i * 4 + 0] += p * vv.x;
                acc[i * 4 + 1] += p * vv.y;
                acc[i * 4 + 2] += p * vv.z;
                acc[i * 4 + 3] += p * vv.w;
            }
        }
    }

    float inv_l = 1.f / l;
    // output layout [b, t, h, d]
    float* ob = out + (((size_t)(b * T_SEQ + qrow)) * N_HEADS + h) * HD;
    #pragma unroll
    for (int i = 0; i < 8; i++) {
        float4 vv = make_float4(acc[i*4+0] * inv_l, acc[i*4+1] * inv_l,
                                acc[i*4+2] * inv_l, acc[i*4+3] * inv_l);
        *(float4*)&ob[(g + 4 * i) * 4] = vv;
    }
}

// ---------------- launch ----------------
extern "C" void kernel_launch(void* const* d_in, const int* in_sizes, int n_in,
                              void* d_out, int out_size)
{
    const float* x   = (const float*)d_in[0];
    const float* w_q = (const float*)d_in[1];
    const float* w_k = (const float*)d_in[2];
    const float* w_v = (const float*)d_in[3];
    const float* w_o = (const float*)d_in[4];
    float* out = (float*)d_out;

    float *q, *k, *v, *attn;
    cudaGetSymbolAddress((void**)&q,    g_q);
    cudaGetSymbolAddress((void**)&k,    g_k);
    cudaGetSymbolAddress((void**)&v,    g_v);
    cudaGetSymbolAddress((void**)&attn, g_attn);

    const int M = B_SZ * T_SEQ;   // 4096

    // QKV projections, scattered to [b, heads, t, d]
    sgemm_tn<1><<<dim3((N_HEADS*HD)/128, M/128), 256>>>(x, w_q, q, M, N_HEADS*HD, D_MODEL, N_HEADS);
    sgemm_tn<1><<<dim3((N_KV*HD)/128,   M/128), 256>>>(x, w_k, k, M, N_KV*HD,   D_MODEL, N_KV);
    sgemm_tn<1><<<dim3((N_KV*HD)/128,   M/128), 256>>>(x, w_v, v, M, N_KV*HD,   D_MODEL, N_KV);

    // RoPE on q and k
    {
        long qp = (long)B_SZ * N_HEADS * T_SEQ * 64;
        long kp = (long)B_SZ * N_KV   * T_SEQ * 64;
        rope_kernel<<<(unsigned)((qp + 255) / 256), 256>>>(q, qp);
        rope_kernel<<<(unsigned)((kp + 255) / 256), 256>>>(k, kp);
    }

    // attention
    cudaFuncSetAttribute(attn_kernel, cudaFuncAttributeMaxDynamicSharedMemorySize, SM_ATT);
    attn_kernel<<<dim3(T_SEQ / BM, B_SZ * N_HEADS), 256, SM_ATT>>>(q, k, v, attn);

    // output projection -> d_out [b, t, D_MODEL]
    sgemm_tn<0><<<dim3(D_MODEL/128, M/128), 256>>>(attn, w_o, out, M, D_MODEL, D_MODEL, 0);
}

// round 3
// speedup vs baseline: 1.6253x; 1.6253x over previous
#include <cuda_runtime.h>
#include <cuda_bf16.h>
#include <math.h>
#include <stdint.h>

#define B_SZ    2
#define T_SEQ   2048
#define D_MODEL 2048
#define N_HEADS 16
#define N_KV    4
#define HD      128
#define KDIM    2048
#define MROWS   (B_SZ * T_SEQ)          // 4096

// ---------------- scratch (static device globals; no allocs) ----------------
__device__ float g_q[(size_t)B_SZ * N_HEADS * T_SEQ * HD];
__device__ float g_k[(size_t)B_SZ * N_KV   * T_SEQ * HD];
__device__ float g_v[(size_t)B_SZ * N_KV   * T_SEQ * HD];
__device__ float g_attn[(size_t)MROWS * D_MODEL];

__device__ __nv_bfloat16 g_xh[(size_t)MROWS * KDIM];
__device__ __nv_bfloat16 g_xl[(size_t)MROWS * KDIM];
__device__ __nv_bfloat16 g_wh[(size_t)3072 * KDIM];   // wq|wk|wv stacked
__device__ __nv_bfloat16 g_wl[(size_t)3072 * KDIM];
__device__ __nv_bfloat16 g_woh[(size_t)2048 * KDIM];
__device__ __nv_bfloat16 g_wol[(size_t)2048 * KDIM];
__device__ __nv_bfloat16 g_ah[(size_t)MROWS * KDIM];
__device__ __nv_bfloat16 g_al[(size_t)MROWS * KDIM];

// ---------------- helpers ----------------
__device__ __forceinline__ uint32_t smem_to_u32(const void* p) {
    uint32_t a;
    asm("{ .reg .u64 t; cvta.to.shared.u64 t, %1; cvt.u32.u64 %0, t; }" : "=r"(a) : "l"(p));
    return a;
}
#define SW128(off) ((off) ^ (((off) >> 3) & 0x70))

__device__ __forceinline__ void cp16(uint32_t saddr, const void* g) {
    asm volatile("cp.async.cg.shared.global [%0], [%1], 16;\n" :: "r"(saddr), "l"(g));
}
#define LDSM_X4(r, a) \
    asm volatile("ldmatrix.sync.aligned.m8n8.x4.shared.b16 {%0,%1,%2,%3}, [%4];" \
        : "=r"((r)[0]), "=r"((r)[1]), "=r"((r)[2]), "=r"((r)[3]) : "r"(a))
#define MMA16816(c, a, b0, b1) \
    asm volatile("mma.sync.aligned.m16n8k16.row.col.f32.bf16.bf16.f32 " \
        "{%0,%1,%2,%3}, {%4,%5,%6,%7}, {%8,%9}, {%0,%1,%2,%3};" \
        : "+f"((c)[0]), "+f"((c)[1]), "+f"((c)[2]), "+f"((c)[3]) \
        : "r"((a)[0]), "r"((a)[1]), "r"((a)[2]), "r"((a)[3]), "r"(b0), "r"(b1))

// ---------------- fp32 -> bf16 hi/lo split ----------------
__global__ void convert_hilo(const float* __restrict__ src,
                             __nv_bfloat16* __restrict__ hi,
                             __nv_bfloat16* __restrict__ lo, int n4)
{
    int i = blockIdx.x * blockDim.x + threadIdx.x;
    if (i >= n4) return;
    float4 v = ((const float4*)src)[i];
    __nv_bfloat16 h0 = __float2bfloat16(v.x), h1 = __float2bfloat16(v.y);
    __nv_bfloat16 h2 = __float2bfloat16(v.z), h3 = __float2bfloat16(v.w);
    __nv_bfloat16 l0 = __float2bfloat16(v.x - __bfloat162float(h0));
    __nv_bfloat16 l1 = __float2bfloat16(v.y - __bfloat162float(h1));
    __nv_bfloat16 l2 = __float2bfloat16(v.z - __bfloat162float(h2));
    __nv_bfloat16 l3 = __float2bfloat16(v.w - __bfloat162float(h3));
    ((__nv_bfloat162*)hi)[2 * i]     = __nv_bfloat162(h0, h1);
    ((__nv_bfloat162*)hi)[2 * i + 1] = __nv_bfloat162(h2, h3);
    ((__nv_bfloat162*)lo)[2 * i]     = __nv_bfloat162(l0, l1);
    ((__nv_bfloat162*)lo)[2 * i + 1] = __nv_bfloat162(l2, l3);
}

// ---------------- mma.sync split-bf16 GEMM: C[M,N] = A @ B^T ----------------
// Tile 128x128, BK=64 (128B rows, SW128). 8 warps, each 32(M)x64(N).
// MODE 0: C row-major N=2048.  MODE 1: scatter cols [0,3072) to g_q/g_k/g_v.
#define OFF_AH 0
#define OFF_AL 16384
#define OFF_BH 32768
#define OFF_BL 49152
#define STAGE_BYTES 65536
#define GEMM_SMEM (2 * STAGE_BYTES)

template<int MODE>
__global__ __launch_bounds__(256, 1)
void gemm_mma(const __nv_bfloat16* __restrict__ Ah, const __nv_bfloat16* __restrict__ Al,
              const __nv_bfloat16* __restrict__ Bh, const __nv_bfloat16* __restrict__ Bl,
              float* __restrict__ C)
{
    extern __shared__ __align__(1024) char smem[];
    const uint32_t sb = smem_to_u32(smem);
    const int tid  = threadIdx.x;
    const int wid  = tid >> 5;
    const int lane = tid & 31;
    const int warp_m = (wid & 3) * 32;
    const int warp_n = (wid >> 2) * 64;
    const int bm0 = blockIdx.y * 128;
    const int bn0 = blockIdx.x * 128;

    float acc[2][8][4];
    #pragma unroll
    for (int mt = 0; mt < 2; mt++)
        #pragma unroll
        for (int nt = 0; nt < 8; nt++)
            #pragma unroll
            for (int i = 0; i < 4; i++) acc[mt][nt][i] = 0.f;

    auto load_chunk = [&](int c) {
        uint32_t st = sb + (uint32_t)(c & 1) * STAGE_BYTES;
        int k0 = c * 64;
        #pragma unroll
        for (int j = 0; j < 4; j++) {
            int i = tid + j * 256;
            int row = i >> 3, cb = (i & 7) * 16;
            uint32_t so = SW128((uint32_t)(row * 128 + cb));
            size_t goA = ((size_t)(bm0 + row) * KDIM + k0) * 2 + cb;
            size_t goB = ((size_t)(bn0 + row) * KDIM + k0) * 2 + cb;
            cp16(st + OFF_AH + so, (const char*)Ah + goA);
            cp16(st + OFF_AL + so, (const char*)Al + goA);
            cp16(st + OFF_BH + so, (const char*)Bh + goB);
            cp16(st + OFF_BL + so, (const char*)Bl + goB);
        }
        asm volatile("cp.async.commit_group;\n");
    };

    load_chunk(0);

    const int NC = KDIM / 64;
    for (int c = 0; c < NC; c++) {
        if (c + 1 < NC) {
            load_chunk(c + 1);
            asm volatile("cp.async.wait_group 1;\n");
        } else {
            asm volatile("cp.async.wait_group 0;\n");
        }
        __syncthreads();

        uint32_t st = sb + (uint32_t)(c & 1) * STAGE_BYTES;
        #pragma unroll
        for (int ks = 0; ks < 4; ks++) {
            uint32_t ah[2][4], al[2][4], bh[4][4], bl[4][4];
            int lrow = (lane & 7) + ((lane >> 3) & 1) * 8;
            int lcb  = ks * 32 + (lane >> 4) * 16;
            #pragma unroll
            for (int mt = 0; mt < 2; mt++) {
                int arow = warp_m + mt * 16 + lrow;
                uint32_t ad = st + OFF_AH + SW128((uint32_t)(arow * 128 + lcb));
                LDSM_X4(ah[mt], ad);
                LDSM_X4(al[mt], ad + (OFF_AL - OFF_AH));
            }
            #pragma unroll
            for (int nt = 0; nt < 4; nt++) {
                int brow = warp_n + nt * 16 + lrow;
                uint32_t bd = st + OFF_BH + SW128((uint32_t)(brow * 128 + lcb));
                LDSM_X4(bh[nt], bd);
                LDSM_X4(bl[nt], bd + (OFF_BL - OFF_BH));
            }
            #pragma unroll
            for (int mt = 0; mt < 2; mt++) {
                #pragma unroll
                for (int nt4 = 0; nt4 < 4; nt4++) {
                    // even n8 tile: regs {0,2}; odd n8 tile: regs {1,3}
                    MMA16816(acc[mt][2*nt4],   ah[mt], bh[nt4][0], bh[nt4][2]);
                    MMA16816(acc[mt][2*nt4],   ah[mt], bl[nt4][0], bl[nt4][2]);
                    MMA16816(acc[mt][2*nt4],   al[mt], bh[nt4][0], bh[nt4][2]);
                    MMA16816(acc[mt][2*nt4+1], ah[mt], bh[nt4][1], bh[nt4][3]);
                    MMA16816(acc[mt][2*nt4+1], ah[mt], bl[nt4][1], bl[nt4][3]);
                    MMA16816(acc[mt][2*nt4+1], al[mt], bh[nt4][1], bh[nt4][3]);
                }
            }
        }
        __syncthreads();
    }

    // epilogue
    const int rbase = bm0 + warp_m + (lane >> 2);
    const int cbase = bn0 + warp_n + (lane & 3) * 2;
    #pragma unroll
    for (int mt = 0; mt < 2; mt++) {
        #pragma unroll
        for (int hh = 0; hh < 2; hh++) {
            int row = rbase + mt * 16 + hh * 8;
            #pragma unroll
            for (int nt = 0; nt < 8; nt++) {
                int col = cbase + nt * 8;
                float2 v = make_float2(acc[mt][nt][2*hh], acc[mt][nt][2*hh+1]);
                if (MODE == 0) {
                    *(float2*)&C[(size_t)row * 2048 + col] = v;
                } else {
                    int b = row >> 11, tq = row & (T_SEQ - 1), d = col & 127;
                    float* base;
                    if (col < 2048) {
                        int h = col >> 7;
                        base = g_q + (((size_t)(b * N_HEADS + h) * T_SEQ + tq) * HD + d);
                    } else if (col < 2560) {
                        int h = (col - 2048) >> 7;
                        base = g_k + (((size_t)(b * N_KV + h) * T_SEQ + tq) * HD + d);
                    } else {
                        int h = (col - 2560) >> 7;
                        base = g_v + (((size_t)(b * N_KV + h) * T_SEQ + tq) * HD + d);
                    }
                    *(float2*)base = v;
                }
            }
        }
    }
}

// ---------------- RoPE (fp32, in place, layout [b, heads, t, d]) ----------------
__global__ void rope_kernel(float* __restrict__ x, long total_pairs)
{
    long idx = (long)blockIdx.x * blockDim.x + threadIdx.x;
    if (idx >= total_pairs) return;
    int  i   = (int)(idx & 63);
    long row = idx >> 6;
    int  tpos = (int)(row & (T_SEQ - 1));
    float* p = x + row * HD;
    float inv = __expf(-((float)i / 64.0f) * 13.815510557964274f);
    float s, c;
    sincosf((float)tpos * inv, &s, &c);
    float x1 = p[i], x2 = p[i + 64];
    p[i]      = x1 * c - x2 * s;
    p[i + 64] = x2 * c + x1 * s;
}

// ---------------- Flash attention (fp32, causal, GQA) ----------------
#define BM 64
#define BN 64
#define KSTR 132
#define PSTR 65
#define SM_ATT ((3 * BM * KSTR + BM * PSTR) * 4)

__global__ __launch_bounds__(256)
void attn_kernel(const float* __restrict__ q, const float* __restrict__ k,
                 const float* __restrict__ v, float* __restrict__ out)
{
    extern __shared__ float smemf[];
    float* Qs = smemf;
    float* Ks = Qs + BM * KSTR;
    float* Vs = Ks + BM * KSTR;
    float* Ps = Vs + BM * KSTR;

    const int qt = (gridDim.x - 1) - blockIdx.x;
    const int bh = blockIdx.y;
    const int b  = bh / N_HEADS;
    const int h  = bh % N_HEADS;
    const int kvh = h / (N_HEADS / N_KV);

    const float* qb = q + ((size_t)bh * T_SEQ + (size_t)qt * BM) * HD;
    const float* kb = k + ((size_t)(b * N_KV + kvh)) * T_SEQ * HD;
    const float* vb = v + ((size_t)(b * N_KV + kvh)) * T_SEQ * HD;

    const int t = threadIdx.x;
    const int r = t >> 2;
    const int g = t & 3;

    for (int i = t; i < BM * (HD / 4); i += 256) {
        int rr = i >> 5;
        int c4 = (i & 31) * 4;
        *(float4*)&Qs[rr * KSTR + c4] = *(const float4*)(qb + (size_t)rr * HD + c4);
    }

    float m = -3.0e38f, l = 0.f;
    float acc[32];
    #pragma unroll
    for (int i = 0; i < 32; i++) acc[i] = 0.f;

    const float scale = 0.08838834764831845f;

    for (int kt = 0; kt <= qt; kt++) {
        __syncthreads();
        for (int i = t; i < BN * (HD / 4); i += 256) {
            int rr = i >> 5;
            int c4 = (i & 31) * 4;
            size_t go = ((size_t)(kt * BN + rr)) * HD + c4;
            *(float4*)&Ks[rr * KSTR + c4] = *(const float4*)(kb + go);
            *(float4*)&Vs[rr * KSTR + c4] = *(const float4*)(vb + go);
        }
        __syncthreads();

        float s[16];
        #pragma unroll
        for (int j = 0; j < 16; j++) s[j] = 0.f;
        #pragma unroll 4
        for (int d4 = 0; d4 < 32; d4++) {
            float4 qv = *(const float4*)&Qs[r * KSTR + d4 * 4];
            #pragma unroll
            for (int j = 0; j < 16; j++) {
                float4 kv = *(const float4*)&Ks[(4 * j + g) * KSTR + d4 * 4];
                s[j] += qv.x * kv.x + qv.y * kv.y + qv.z * kv.z + qv.w * kv.w;
            }
        }

        const bool diag = (kt == qt);
        float mloc = -3.0e38f;
        #pragma unroll
        for (int j = 0; j < 16; j++) {
            float sv = s[j] * scale;
            if (diag && (4 * j + g) > r) sv = -3.0e38f;
            s[j] = sv;
            mloc = fmaxf(mloc, sv);
        }
        mloc = fmaxf(mloc, __shfl_xor_sync(0xffffffffu, mloc, 1));
        mloc = fmaxf(mloc, __shfl_xor_sync(0xffffffffu, mloc, 2));
        float mnew = fmaxf(m, mloc);
        float corr = __expf(m - mnew);
        float psum = 0.f;
        #pragma unroll
        for (int j = 0; j < 16; j++) {
            float p = __expf(s[j] - mnew);
            psum += p;
            Ps[r * PSTR + 4 * j + g] = p;
        }
        psum += __shfl_xor_sync(0xffffffffu, psum, 1);
        psum += __shfl_xor_sync(0xffffffffu, psum, 2);
        l = l * corr + psum;
        m = mnew;
        #pragma unroll
        for (int i = 0; i < 32; i++) acc[i] *= corr;

        __syncwarp();

        #pragma unroll 2
        for (int j = 0; j < BN; j++) {
            float p = Ps[r * PSTR + j];
            #pragma unroll
            for (int i = 0; i < 8; i++) {
                float4 vv = *(const float4*)&Vs[j * KSTR + (g + 4 * i) * 4];
                acc[i * 4 + 0] += p * vv.x;
                acc[i * 4 + 1] += p * vv.y;
                acc[i * 4 + 2] += p * vv.z;
                acc[i * 4 + 3] += p * vv.w;
            }
        }
    }

    float inv_l = 1.f / l;
    const int qrow = qt * BM + r;
    float* ob = out + (((size_t)(b * T_SEQ + qrow)) * N_HEADS + h) * HD;
    #pragma unroll
    for (int i = 0; i < 8; i++) {
        float4 vv = make_float4(acc[i*4+0] * inv_l, acc[i*4+1] * inv_l,
                                acc[i*4+2] * inv_l, acc[i*4+3] * inv_l);
        *(float4*)&ob[(g + 4 * i) * 4] = vv;
    }
}

// ---------------- launch ----------------
extern "C" void kernel_launch(void* const* d_in, const int* in_sizes, int n_in,
                              void* d_out, int out_size)
{
    const float* x   = (const float*)d_in[0];
    const float* w_q = (const float*)d_in[1];
    const float* w_k = (const float*)d_in[2];
    const float* w_v = (const float*)d_in[3];
    const float* w_o = (const float*)d_in[4];
    float* out = (float*)d_out;

    float *q, *k, *v, *attn;
    __nv_bfloat16 *xh, *xl, *wh, *wl, *woh, *wol, *ah, *al;
    cudaGetSymbolAddress((void**)&q,    g_q);
    cudaGetSymbolAddress((void**)&k,    g_k);
    cudaGetSymbolAddress((void**)&v,    g_v);
    cudaGetSymbolAddress((void**)&attn, g_attn);
    cudaGetSymbolAddress((void**)&xh,   g_xh);
    cudaGetSymbolAddress((void**)&xl,   g_xl);
    cudaGetSymbolAddress((void**)&wh,   g_wh);
    cudaGetSymbolAddress((void**)&wl,   g_wl);
    cudaGetSymbolAddress((void**)&woh,  g_woh);
    cudaGetSymbolAddress((void**)&wol,  g_wol);
    cudaGetSymbolAddress((void**)&ah,   g_ah);
    cudaGetSymbolAddress((void**)&al,   g_al);

    // input conversions to bf16 hi/lo
    {
        int n4;
        n4 = MROWS * KDIM / 4;
        convert_hilo<<<(n4 + 255) / 256, 256>>>(x, xh, xl, n4);
        n4 = 2048 * KDIM / 4;
        convert_hilo<<<(n4 + 255) / 256, 256>>>(w_q, wh, wl, n4);
        n4 = 512 * KDIM / 4;
        convert_hilo<<<(n4 + 255) / 256, 256>>>(w_k, wh + (size_t)2048 * KDIM, wl + (size_t)2048 * KDIM, n4);
        convert_hilo<<<(n4 + 255) / 256, 256>>>(w_v, wh + (size_t)2560 * KDIM, wl + (size_t)2560 * KDIM, n4);
        n4 = 2048 * KDIM / 4;
        convert_hilo<<<(n4 + 255) / 256, 256>>>(w_o, woh, wol, n4);
    }

    cudaFuncSetAttribute(gemm_mma<0>, cudaFuncAttributeMaxDynamicSharedMemorySize, GEMM_SMEM);
    cudaFuncSetAttribute(gemm_mma<1>, cudaFuncAttributeMaxDynamicSharedMemorySize, GEMM_SMEM);

    // fused QKV projection (N = 3072) with scatter epilogue
    gemm_mma<1><<<dim3(3072 / 128, MROWS / 128), 256, GEMM_SMEM>>>(xh, xl, wh, wl, q);

    // RoPE
    {
        long qp = (long)B_SZ * N_HEADS * T_SEQ * 64;
        long kp = (long)B_SZ * N_KV   * T_SEQ * 64;
        rope_kernel<<<(unsigned)((qp + 255) / 256), 256>>>(q, qp);
        rope_kernel<<<(unsigned)((kp + 255) / 256), 256>>>(k, kp);
    }

    // attention
    cudaFuncSetAttribute(attn_kernel, cudaFuncAttributeMaxDynamicSharedMemorySize, SM_ATT);
    attn_kernel<<<dim3(T_SEQ / BM, B_SZ * N_HEADS), 256, SM_ATT>>>(q, k, v, attn);

    // attn -> bf16 hi/lo, then O projection
    {
        int n4 = MROWS * KDIM / 4;
        convert_hilo<<<(n4 + 255) / 256, 256>>>(attn, ah, al, n4);
    }
    gemm_mma<0><<<dim3(2048 / 128, MROWS / 128), 256, GEMM_SMEM>>>(ah, al, woh, wol, out);
}

// round 4
// speedup vs baseline: 4.6627x; 2.8688x over previous
#include <cuda_runtime.h>
#include <cuda_bf16.h>
#include <math.h>
#include <stdint.h>

#define B_SZ    2
#define T_SEQ   2048
#define D_MODEL 2048
#define N_HEADS 16
#define N_KV    4
#define HD      128
#define KDIM    2048
#define MROWS   (B_SZ * T_SEQ)          // 4096

// ---------------- scratch (static device globals; no allocs) ----------------
__device__ float g_q[(size_t)B_SZ * N_HEADS * T_SEQ * HD];
__device__ float g_k[(size_t)B_SZ * N_KV   * T_SEQ * HD];
__device__ float g_v[(size_t)B_SZ * N_KV   * T_SEQ * HD];

__device__ __nv_bfloat16 g_xh[(size_t)MROWS * KDIM];
__device__ __nv_bfloat16 g_xl[(size_t)MROWS * KDIM];
__device__ __nv_bfloat16 g_wh[(size_t)3072 * KDIM];   // wq|wk|wv stacked
__device__ __nv_bfloat16 g_wl[(size_t)3072 * KDIM];
__device__ __nv_bfloat16 g_woh[(size_t)2048 * KDIM];
__device__ __nv_bfloat16 g_wol[(size_t)2048 * KDIM];
__device__ __nv_bfloat16 g_ah[(size_t)MROWS * KDIM];  // attention out hi/lo
__device__ __nv_bfloat16 g_al[(size_t)MROWS * KDIM];

__device__ __nv_bfloat16 g_qh[(size_t)B_SZ * N_HEADS * T_SEQ * HD];
__device__ __nv_bfloat16 g_ql[(size_t)B_SZ * N_HEADS * T_SEQ * HD];
__device__ __nv_bfloat16 g_kh[(size_t)B_SZ * N_KV * T_SEQ * HD];
__device__ __nv_bfloat16 g_kl[(size_t)B_SZ * N_KV * T_SEQ * HD];
__device__ __nv_bfloat16 g_vh[(size_t)B_SZ * N_KV * T_SEQ * HD];
__device__ __nv_bfloat16 g_vl[(size_t)B_SZ * N_KV * T_SEQ * HD];

// ---------------- helpers ----------------
__device__ __forceinline__ uint32_t smem_to_u32(const void* p) {
    uint32_t a;
    asm("{ .reg .u64 t; cvta.to.shared.u64 t, %1; cvt.u32.u64 %0, t; }" : "=r"(a) : "l"(p));
    return a;
}
#define SW128(off) ((off) ^ (((off) >> 3) & 0x70))

__device__ __forceinline__ void cp16(uint32_t saddr, const void* g) {
    asm volatile("cp.async.cg.shared.global [%0], [%1], 16;\n" :: "r"(saddr), "l"(g));
}
#define LDSM_X4(r, a) \
    asm volatile("ldmatrix.sync.aligned.m8n8.x4.shared.b16 {%0,%1,%2,%3}, [%4];" \
        : "=r"((r)[0]), "=r"((r)[1]), "=r"((r)[2]), "=r"((r)[3]) : "r"(a))
#define LDSM_X4_T(r, a) \
    asm volatile("ldmatrix.sync.aligned.m8n8.x4.trans.shared.b16 {%0,%1,%2,%3}, [%4];" \
        : "=r"((r)[0]), "=r"((r)[1]), "=r"((r)[2]), "=r"((r)[3]) : "r"(a))
#define MMA16816(c, a, b0, b1) \
    asm volatile("mma.sync.aligned.m16n8k16.row.col.f32.bf16.bf16.f32 " \
        "{%0,%1,%2,%3}, {%4,%5,%6,%7}, {%8,%9}, {%0,%1,%2,%3};" \
        : "+f"((c)[0]), "+f"((c)[1]), "+f"((c)[2]), "+f"((c)[3]) \
        : "r"((a)[0]), "r"((a)[1]), "r"((a)[2]), "r"((a)[3]), "r"(b0), "r"(b1))

__device__ __forceinline__ uint32_t packbf(float a, float b) {
    __nv_bfloat162 t = __floats2bfloat162_rn(a, b);
    return reinterpret_cast<uint32_t&>(t);
}

// ---------------- fp32 -> bf16 hi/lo split ----------------
__global__ void convert_hilo(const float* __restrict__ src,
                             __nv_bfloat16* __restrict__ hi,
                             __nv_bfloat16* __restrict__ lo, int n4)
{
    int i = blockIdx.x * blockDim.x + threadIdx.x;
    if (i >= n4) return;
    float4 v = ((const float4*)src)[i];
    __nv_bfloat16 h0 = __float2bfloat16(v.x), h1 = __float2bfloat16(v.y);
    __nv_bfloat16 h2 = __float2bfloat16(v.z), h3 = __float2bfloat16(v.w);
    __nv_bfloat16 l0 = __float2bfloat16(v.x - __bfloat162float(h0));
    __nv_bfloat16 l1 = __float2bfloat16(v.y - __bfloat162float(h1));
    __nv_bfloat16 l2 = __float2bfloat16(v.z - __bfloat162float(h2));
    __nv_bfloat16 l3 = __float2bfloat16(v.w - __bfloat162float(h3));
    ((__nv_bfloat162*)hi)[2 * i]     = __nv_bfloat162(h0, h1);
    ((__nv_bfloat162*)hi)[2 * i + 1] = __nv_bfloat162(h2, h3);
    ((__nv_bfloat162*)lo)[2 * i]     = __nv_bfloat162(l0, l1);
    ((__nv_bfloat162*)lo)[2 * i + 1] = __nv_bfloat162(l2, l3);
}

// ---------------- mma.sync split-bf16 GEMM: C[M,N] = A @ B^T ----------------
#define OFF_AH 0
#define OFF_AL 16384
#define OFF_BH 32768
#define OFF_BL 49152
#define STAGE_BYTES 65536
#define GEMM_SMEM (2 * STAGE_BYTES)

template<int MODE>
__global__ __launch_bounds__(256, 1)
void gemm_mma(const __nv_bfloat16* __restrict__ Ah, const __nv_bfloat16* __restrict__ Al,
              const __nv_bfloat16* __restrict__ Bh, const __nv_bfloat16* __restrict__ Bl,
              float* __restrict__ C)
{
    extern __shared__ __align__(1024) char smem[];
    const uint32_t sb = smem_to_u32(smem);
    const int tid  = threadIdx.x;
    const int wid  = tid >> 5;
    const int lane = tid & 31;
    const int warp_m = (wid & 3) * 32;
    const int warp_n = (wid >> 2) * 64;
    const int bm0 = blockIdx.y * 128;
    const int bn0 = blockIdx.x * 128;

    float acc[2][8][4];
    #pragma unroll
    for (int mt = 0; mt < 2; mt++)
        #pragma unroll
        for (int nt = 0; nt < 8; nt++)
            #pragma unroll
            for (int i = 0; i < 4; i++) acc[mt][nt][i] = 0.f;

    auto load_chunk = [&](int c) {
        uint32_t st = sb + (uint32_t)(c & 1) * STAGE_BYTES;
        int k0 = c * 64;
        #pragma unroll
        for (int j = 0; j < 4; j++) {
            int i = tid + j * 256;
            int row = i >> 3, cb = (i & 7) * 16;
            uint32_t so = SW128((uint32_t)(row * 128 + cb));
            size_t goA = ((size_t)(bm0 + row) * KDIM + k0) * 2 + cb;
            size_t goB = ((size_t)(bn0 + row) * KDIM + k0) * 2 + cb;
            cp16(st + OFF_AH + so, (const char*)Ah + goA);
            cp16(st + OFF_AL + so, (const char*)Al + goA);
            cp16(st + OFF_BH + so, (const char*)Bh + goB);
            cp16(st + OFF_BL + so, (const char*)Bl + goB);
        }
        asm volatile("cp.async.commit_group;\n");
    };

    load_chunk(0);

    const int NC = KDIM / 64;
    for (int c = 0; c < NC; c++) {
        if (c + 1 < NC) {
            load_chunk(c + 1);
            asm volatile("cp.async.wait_group 1;\n");
        } else {
            asm volatile("cp.async.wait_group 0;\n");
        }
        __syncthreads();

        uint32_t st = sb + (uint32_t)(c & 1) * STAGE_BYTES;
        #pragma unroll
        for (int ks = 0; ks < 4; ks++) {
            uint32_t ah[2][4], al[2][4], bh[4][4], bl[4][4];
            int lrow = (lane & 7) + ((lane >> 3) & 1) * 8;
            int lcb  = ks * 32 + (lane >> 4) * 16;
            #pragma unroll
            for (int mt = 0; mt < 2; mt++) {
                int arow = warp_m + mt * 16 + lrow;
                uint32_t ad = st + OFF_AH + SW128((uint32_t)(arow * 128 + lcb));
                LDSM_X4(ah[mt], ad);
                LDSM_X4(al[mt], ad + (OFF_AL - OFF_AH));
            }
            #pragma unroll
            for (int nt = 0; nt < 4; nt++) {
                int brow = warp_n + nt * 16 + lrow;
                uint32_t bd = st + OFF_BH + SW128((uint32_t)(brow * 128 + lcb));
                LDSM_X4(bh[nt], bd);
                LDSM_X4(bl[nt], bd + (OFF_BL - OFF_BH));
            }
            #pragma unroll
            for (int mt = 0; mt < 2; mt++) {
                #pragma unroll
                for (int nt4 = 0; nt4 < 4; nt4++) {
                    MMA16816(acc[mt][2*nt4],   ah[mt], bh[nt4][0], bh[nt4][2]);
                    MMA16816(acc[mt][2*nt4],   ah[mt], bl[nt4][0], bl[nt4][2]);
                    MMA16816(acc[mt][2*nt4],   al[mt], bh[nt4][0], bh[nt4][2]);
                    MMA16816(acc[mt][2*nt4+1], ah[mt], bh[nt4][1], bh[nt4][3]);
                    MMA16816(acc[mt][2*nt4+1], ah[mt], bl[nt4][1], bl[nt4][3]);
                    MMA16816(acc[mt][2*nt4+1], al[mt], bh[nt4][1], bh[nt4][3]);
                }
            }
        }
        __syncthreads();
    }

    const int rbase = bm0 + warp_m + (lane >> 2);
    const int cbase = bn0 + warp_n + (lane & 3) * 2;
    #pragma unroll
    for (int mt = 0; mt < 2; mt++) {
        #pragma unroll
        for (int hh = 0; hh < 2; hh++) {
            int row = rbase + mt * 16 + hh * 8;
            #pragma unroll
            for (int nt = 0; nt < 8; nt++) {
                int col = cbase + nt * 8;
                float2 v = make_float2(acc[mt][nt][2*hh], acc[mt][nt][2*hh+1]);
                if (MODE == 0) {
                    *(float2*)&C[(size_t)row * 2048 + col] = v;
                } else {
                    int b = row >> 11, tq = row & (T_SEQ - 1), d = col & 127;
                    float* base;
                    if (col < 2048) {
                        int h = col >> 7;
                        base = g_q + (((size_t)(b * N_HEADS + h) * T_SEQ + tq) * HD + d);
                    } else if (col < 2560) {
                        int h = (col - 2048) >> 7;
                        base = g_k + (((size_t)(b * N_KV + h) * T_SEQ + tq) * HD + d);
                    } else {
                        int h = (col - 2560) >> 7;
                        base = g_v + (((size_t)(b * N_KV + h) * T_SEQ + tq) * HD + d);
                    }
                    *(float2*)base = v;
                }
            }
        }
    }
}

// ---------------- RoPE: fp32 in -> rotated, scaled bf16 hi/lo out ----------------
__global__ void rope_split(const float* __restrict__ src,
                           __nv_bfloat16* __restrict__ hi,
                           __nv_bfloat16* __restrict__ lo,
                           long total_pairs, float scale)
{
    long idx = (long)blockIdx.x * blockDim.x + threadIdx.x;
    if (idx >= total_pairs) return;
    int  i   = (int)(idx & 63);
    long row = idx >> 6;
    int  tpos = (int)(row & (T_SEQ - 1));
    const float* p = src + row * HD;
    float inv = __expf(-((float)i / 64.0f) * 13.815510557964274f);
    float s, c;
    sincosf((float)tpos * inv, &s, &c);
    float x1 = p[i], x2 = p[i + 64];
    float r1 = (x1 * c - x2 * s) * scale;
    float r2 = (x2 * c + x1 * s) * scale;
    __nv_bfloat16 h1 = __float2bfloat16(r1), h2 = __float2bfloat16(r2);
    hi[row * HD + i]      = h1;
    hi[row * HD + i + 64] = h2;
    lo[row * HD + i]      = __float2bfloat16(r1 - __bfloat162float(h1));
    lo[row * HD + i + 64] = __float2bfloat16(r2 - __bfloat162float(h2));
}

// ---------------- tensor-core flash attention (split-bf16, causal, GQA) ----------
// Block: BM=128 q-rows for one (b,h); 8 warps x 16 rows. BN=64 kv per iter.
// smem rows: 128 bf16 = 256B; swizzle: chunk c (16B) -> c ^ (row & 7)
#define ATT_QH 0
#define ATT_QL 32768
#define ATT_ST0 65536
#define ATT_STAGE 65536
#define ATT_KH 0
#define ATT_KL 16384
#define ATT_VH 32768
#define ATT_VL 49152
#define ATT_SMEM (ATT_ST0 + 2 * ATT_STAGE)   // 196608

__device__ __forceinline__ uint32_t swz256(int row, int cb) {
    return (uint32_t)(row * 256 + ((cb ^ (row & 7)) << 4));
}

__global__ __launch_bounds__(256, 1)
void attn_mma(const __nv_bfloat16* __restrict__ qh, const __nv_bfloat16* __restrict__ ql,
              const __nv_bfloat16* __restrict__ kh, const __nv_bfloat16* __restrict__ kl,
              const __nv_bfloat16* __restrict__ vh, const __nv_bfloat16* __restrict__ vl,
              __nv_bfloat16* __restrict__ oh, __nv_bfloat16* __restrict__ ol)
{
    extern __shared__ __align__(1024) char smem[];
    const uint32_t sb = smem_to_u32(smem);
    const int tid  = threadIdx.x;
    const int w    = tid >> 5;
    const int lane = tid & 31;
    const int qt   = (gridDim.x - 1) - blockIdx.x;
    const int bh   = blockIdx.y;
    const int b    = bh >> 4;
    const int h    = bh & 15;
    const int kvh  = h >> 2;

    const size_t qoff = ((size_t)bh * T_SEQ + (size_t)qt * 128) * HD;
    const size_t koff = (size_t)(b * N_KV + kvh) * T_SEQ * HD;

    // Q tile load (hi+lo): 128 rows x 16 chunks each
    #pragma unroll
    for (int j = 0; j < 8; j++) {
        int i = tid + j * 256;
        int row = i >> 4, cb = i & 15;
        uint32_t so = swz256(row, cb);
        size_t go = (qoff + (size_t)row * HD) * 2 + cb * 16;
        cp16(sb + ATT_QH + so, (const char*)qh + go);
        cp16(sb + ATT_QL + so, (const char*)ql + go);
    }
    auto load_stage = [&](int kt) {
        uint32_t st = sb + ATT_ST0 + (uint32_t)(kt & 1) * ATT_STAGE;
        size_t base = (koff + (size_t)kt * 64 * HD) * 2;
        #pragma unroll
        for (int j = 0; j < 4; j++) {
            int i = tid + j * 256;
            int row = i >> 4, cb = i & 15;
            uint32_t so = swz256(row, cb);
            size_t go = base + (size_t)row * 256 + cb * 16;
            cp16(st + ATT_KH + so, (const char*)kh + go);
            cp16(st + ATT_KL + so, (const char*)kl + go);
            cp16(st + ATT_VH + so, (const char*)vh + go);
            cp16(st + ATT_VL + so, (const char*)vl + go);
        }
        asm volatile("cp.async.commit_group;\n");
    };
    load_stage(0);

    float acc[16][4];
    #pragma unroll
    for (int nt = 0; nt < 16; nt++)
        #pragma unroll
        for (int i = 0; i < 4; i++) acc[nt][i] = 0.f;
    float m0 = -1e30f, m1 = -1e30f, l0 = 0.f, l1 = 0.f;

    const int r4 = lane >> 2;
    const int lrow = (lane & 7) + ((lane >> 3) & 1) * 8;
    const int qrow0 = qt * 128 + 16 * w + r4;
    const int nkt = 2 * (qt + 1);

    for (int kt = 0; kt < nkt; kt++) {
        if (kt + 1 < nkt) {
            load_stage(kt + 1);
            asm volatile("cp.async.wait_group 1;\n");
        } else {
            asm volatile("cp.async.wait_group 0;\n");
        }
        __syncthreads();
        uint32_t st = sb + ATT_ST0 + (uint32_t)(kt & 1) * ATT_STAGE;

        // ---- S = Q K^T ----
        float sacc[8][4];
        #pragma unroll
        for (int nt = 0; nt < 8; nt++)
            #pragma unroll
            for (int i = 0; i < 4; i++) sacc[nt][i] = 0.f;

        #pragma unroll
        for (int ks = 0; ks < 8; ks++) {
            int cb = 2 * ks + (lane >> 4);
            uint32_t aad = sb + ATT_QH + swz256(16 * w + lrow, cb);
            uint32_t ah4[4], al4[4];
            LDSM_X4(ah4, aad);
            LDSM_X4(al4, aad + (ATT_QL - ATT_QH));
            #pragma unroll
            for (int nt2 = 0; nt2 < 4; nt2++) {
                uint32_t bd = st + ATT_KH + swz256(16 * nt2 + lrow, cb);
                uint32_t kh4[4], kl4[4];
                LDSM_X4(kh4, bd);
                LDSM_X4(kl4, bd + (ATT_KL - ATT_KH));
                MMA16816(sacc[2*nt2],   ah4, kh4[0], kh4[2]);
                MMA16816(sacc[2*nt2],   ah4, kl4[0], kl4[2]);
                MMA16816(sacc[2*nt2],   al4, kh4[0], kh4[2]);
                MMA16816(sacc[2*nt2+1], ah4, kh4[1], kh4[3]);
                MMA16816(sacc[2*nt2+1], ah4, kl4[1], kl4[3]);
                MMA16816(sacc[2*nt2+1], al4, kh4[1], kh4[3]);
            }
        }

        // ---- causal mask (scale already folded into q) ----
        int kvbase = kt * 64;
        if (kvbase + 63 > qrow0) {
            #pragma unroll
            for (int nt = 0; nt < 8; nt++) {
                int col = kvbase + 8 * nt + (lane & 3) * 2;
                if (col     > qrow0)     sacc[nt][0] = -1e30f;
                if (col + 1 > qrow0)     sacc[nt][1] = -1e30f;
                if (col     > qrow0 + 8) sacc[nt][2] = -1e30f;
                if (col + 1 > qrow0 + 8) sacc[nt][3] = -1e30f;
            }
        }

        // ---- online softmax ----
        float ml0 = -1e30f, ml1 = -1e30f;
        #pragma unroll
        for (int nt = 0; nt < 8; nt++) {
            ml0 = fmaxf(ml0, fmaxf(sacc[nt][0], sacc[nt][1]));
            ml1 = fmaxf(ml1, fmaxf(sacc[nt][2], sacc[nt][3]));
        }
        ml0 = fmaxf(ml0, __shfl_xor_sync(0xffffffffu, ml0, 1));
        ml0 = fmaxf(ml0, __shfl_xor_sync(0xffffffffu, ml0, 2));
        ml1 = fmaxf(ml1, __shfl_xor_sync(0xffffffffu, ml1, 1));
        ml1 = fmaxf(ml1, __shfl_xor_sync(0xffffffffu, ml1, 2));
        float mn0 = fmaxf(m0, ml0), mn1 = fmaxf(m1, ml1);
        float c0 = __expf(m0 - mn0), c1 = __expf(m1 - mn1);
        float ps0 = 0.f, ps1 = 0.f;
        #pragma unroll
        for (int nt = 0; nt < 8; nt++) {
            sacc[nt][0] = __expf(sacc[nt][0] - mn0);
            sacc[nt][1] = __expf(sacc[nt][1] - mn0);
            sacc[nt][2] = __expf(sacc[nt][2] - mn1);
            sacc[nt][3] = __expf(sacc[nt][3] - mn1);
            ps0 += sacc[nt][0] + sacc[nt][1];
            ps1 += sacc[nt][2] + sacc[nt][3];
        }
        ps0 += __shfl_xor_sync(0xffffffffu, ps0, 1);
        ps0 += __shfl_xor_sync(0xffffffffu, ps0, 2);
        ps1 += __shfl_xor_sync(0xffffffffu, ps1, 1);
        ps1 += __shfl_xor_sync(0xffffffffu, ps1, 2);
        l0 = l0 * c0 + ps0;
        l1 = l1 * c1 + ps1;
        m0 = mn0; m1 = mn1;
        #pragma unroll
        for (int nt = 0; nt < 16; nt++) {
            acc[nt][0] *= c0; acc[nt][1] *= c0;
            acc[nt][2] *= c1; acc[nt][3] *= c1;
        }

        // ---- pack P fragments (hi/lo) ----
        uint32_t ph[4][4], pl[4][4];
        #pragma unroll
        for (int j = 0; j < 4; j++) {
            #pragma unroll
            for (int half = 0; half < 2; half++) {        // even/odd S tile -> a0a1 / a2a3
                float p0 = sacc[2*j+half][0], p1 = sacc[2*j+half][1];
                float p2 = sacc[2*j+half][2], p3 = sacc[2*j+half][3];
                __nv_bfloat16 h0 = __float2bfloat16(p0), h1b = __float2bfloat16(p1);
                __nv_bfloat16 h2 = __float2bfloat16(p2), h3 = __float2bfloat16(p3);
                ph[j][2*half]   = packbf(__bfloat162float(h0), __bfloat162float(h1b));
                ph[j][2*half+1] = packbf(__bfloat162float(h2), __bfloat162float(h3));
                pl[j][2*half]   = packbf(p0 - __bfloat162float(h0), p1 - __bfloat162float(h1b));
                pl[j][2*half+1] = packbf(p2 - __bfloat162float(h2), p3 - __bfloat162float(h3));
            }
        }

        // ---- O += P V ----
        #pragma unroll
        for (int j = 0; j < 4; j++) {
            #pragma unroll
            for (int dt = 0; dt < 8; dt++) {
                int cb = 2 * dt + (lane >> 4);
                uint32_t vd = st + ATT_VH + swz256(16 * j + lrow, cb);
                uint32_t vh4[4], vl4[4];
                LDSM_X4_T(vh4, vd);
                LDSM_X4_T(vl4, vd + (ATT_VL - ATT_VH));
                MMA16816(acc[2*dt],   ph[j], vh4[0], vh4[1]);
                MMA16816(acc[2*dt],   ph[j], vl4[0], vl4[1]);
                MMA16816(acc[2*dt],   pl[j], vh4[0], vh4[1]);
                MMA16816(acc[2*dt+1], ph[j], vh4[2], vh4[3]);
                MMA16816(acc[2*dt+1], ph[j], vl4[2], vl4[3]);
                MMA16816(acc[2*dt+1], pl[j], vh4[2], vh4[3]);
            }
        }
        __syncthreads();
    }

    // ---- epilogue: normalize, split to bf16 hi/lo, write [b*T+t][h*128+d] ----
    float i0 = 1.f / l0, i1 = 1.f / l1;
    const int trow0 = qt * 128 + 16 * w + r4;
    const size_t orow0 = (size_t)(b * T_SEQ + trow0) * 2048 + h * 128;
    const size_t orow1 = orow0 + 8 * 2048;
    #pragma unroll
    for (int nt = 0; nt < 16; nt++) {
        int d = 8 * nt + (lane & 3) * 2;
        float a0 = acc[nt][0] * i0, a1 = acc[nt][1] * i0;
        float a2 = acc[nt][2] * i1, a3 = acc[nt][3] * i1;
        __nv_bfloat16 h0 = __float2bfloat16(a0), h1b = __float2bfloat16(a1);
        __nv_bfloat16 h2 = __float2bfloat16(a2), h3 = __float2bfloat16(a3);
        *(uint32_t*)&oh[orow0 + d] = packbf(__bfloat162float(h0), __bfloat162float(h1b));
        *(uint32_t*)&oh[orow1 + d] = packbf(__bfloat162float(h2), __bfloat162float(h3));
        *(uint32_t*)&ol[orow0 + d] = packbf(a0 - __bfloat162float(h0), a1 - __bfloat162float(h1b));
        *(uint32_t*)&ol[orow1 + d] = packbf(a2 - __bfloat162float(h2), a3 - __bfloat162float(h3));
    }
}

// ---------------- launch ----------------
extern "C" void kernel_launch(void* const* d_in, const int* in_sizes, int n_in,
                              void* d_out, int out_size)
{
    const float* x   = (const float*)d_in[0];
    const float* w_q = (const float*)d_in[1];
    const float* w_k = (const float*)d_in[2];
    const float* w_v = (const float*)d_in[3];
    const float* w_o = (const float*)d_in[4];
    float* out = (float*)d_out;

    float *q, *k, *v;
    __nv_bfloat16 *xh, *xl, *wh, *wl, *woh, *wol, *ah, *al;
    __nv_bfloat16 *qh, *ql, *kh, *kl, *vh, *vl;
    cudaGetSymbolAddress((void**)&q,   g_q);
    cudaGetSymbolAddress((void**)&k,   g_k);
    cudaGetSymbolAddress((void**)&v,   g_v);
    cudaGetSymbolAddress((void**)&xh,  g_xh);
    cudaGetSymbolAddress((void**)&xl,  g_xl);
    cudaGetSymbolAddress((void**)&wh,  g_wh);
    cudaGetSymbolAddress((void**)&wl,  g_wl);
    cudaGetSymbolAddress((void**)&woh, g_woh);
    cudaGetSymbolAddress((void**)&wol, g_wol);
    cudaGetSymbolAddress((void**)&ah,  g_ah);
    cudaGetSymbolAddress((void**)&al,  g_al);
    cudaGetSymbolAddress((void**)&qh,  g_qh);
    cudaGetSymbolAddress((void**)&ql,  g_ql);
    cudaGetSymbolAddress((void**)&kh,  g_kh);
    cudaGetSymbolAddress((void**)&kl,  g_kl);
    cudaGetSymbolAddress((void**)&vh,  g_vh);
    cudaGetSymbolAddress((void**)&vl,  g_vl);

    // input conversions to bf16 hi/lo
    {
        int n4;
        n4 = MROWS * KDIM / 4;
        convert_hilo<<<(n4 + 255) / 256, 256>>>(x, xh, xl, n4);
        n4 = 2048 * KDIM / 4;
        convert_hilo<<<(n4 + 255) / 256, 256>>>(w_q, wh, wl, n4);
        n4 = 512 * KDIM / 4;
        convert_hilo<<<(n4 + 255) / 256, 256>>>(w_k, wh + (size_t)2048 * KDIM, wl + (size_t)2048 * KDIM, n4);
        convert_hilo<<<(n4 + 255) / 256, 256>>>(w_v, wh + (size_t)2560 * KDIM, wl + (size_t)2560 * KDIM, n4);
        n4 = 2048 * KDIM / 4;
        convert_hilo<<<(n4 + 255) / 256, 256>>>(w_o, woh, wol, n4);
    }

    cudaFuncSetAttribute(gemm_mma<0>, cudaFuncAttributeMaxDynamicSharedMemorySize, GEMM_SMEM);
    cudaFuncSetAttribute(gemm_mma<1>, cudaFuncAttributeMaxDynamicSharedMemorySize, GEMM_SMEM);

    // fused QKV projection with scatter epilogue (fp32 q/k/v)
    gemm_mma<1><<<dim3(3072 / 128, MROWS / 128), 256, GEMM_SMEM>>>(xh, xl, wh, wl, q);

    // RoPE -> scaled bf16 hi/lo (scale folded into q), V split
    {
        long qp = (long)B_SZ * N_HEADS * T_SEQ * 64;
        long kp = (long)B_SZ * N_KV   * T_SEQ * 64;
        rope_split<<<(unsigned)((qp + 255) / 256), 256>>>(q, qh, ql, qp, 0.08838834764831845f);
        rope_split<<<(unsigned)((kp + 255) / 256), 256>>>(k, kh, kl, kp, 1.0f);
        int n4 = B_SZ * N_KV * T_SEQ * HD / 4;
        convert_hilo<<<(n4 + 255) / 256, 256>>>(v, vh, vl, n4);
    }

    // tensor-core attention -> g_ah/g_al (bf16 hi/lo, [b*T+t][h*128+d])
    cudaFuncSetAttribute(attn_mma, cudaFuncAttributeMaxDynamicSharedMemorySize, ATT_SMEM);
    attn_mma<<<dim3(T_SEQ / 128, B_SZ * N_HEADS), 256, ATT_SMEM>>>(qh, ql, kh, kl, vh, vl, ah, al);

    // O projection
    gemm_mma<0><<<dim3(2048 / 128, MROWS / 128), 256, GEMM_SMEM>>>(ah, al, woh, wol, out);
}